// round 6
// baseline (speedup 1.0000x reference)
#include <cuda_runtime.h>
#include <cuda_bf16.h>

#define NN 50000
#define EE 800000
#define EP (EE + NN)      // edges + self loops = 850000
#define FIN 64
#define FOUT 256          // HEADS*HID
#define NC 16
#define SCAN_B 512
#define SCAN_NB ((NN + SCAN_B - 1) / SCAN_B)   // 98

// ---------------- scratch (device globals; no allocations allowed) --------
__device__ float4 g_xh1[NN * 64];     // [N,256] layer1 features (as float4)
__device__ float4 g_out1[NN * 64];    // [N,256] layer1 aggregation output
__device__ float4 g_xh2[NN * 4];      // [N,16]  layer2 features
__device__ float4 g_a_src1[NN];       // [N,4]
__device__ float4 g_a_dst1[NN];       // [N,4]
__device__ float4 g_alpha[EP];        // per-edge unnormalized softmax weight (4 heads)
__device__ float4 g_inv1[NN];         // per-node 1/denom (4 heads)
__device__ float  g_a_src2[NN];
__device__ float  g_a_dst2[NN];
__device__ int    g_rowptr[NN + 1];
__device__ int    g_cnt[NN];
__device__ int    g_cur[NN];
__device__ int    g_col[EP];          // CSR: src node per incoming edge of dst
__device__ int    g_is64;             // 1 if edge_index is int64, 0 if int32
__device__ int    g_bsum[SCAN_NB];
__device__ int    g_boff[SCAN_NB];

// ---------------- helpers -------------------------------------------------
__device__ __forceinline__ float wmax(float v) {
#pragma unroll
    for (int o = 16; o; o >>= 1) v = fmaxf(v, __shfl_xor_sync(0xffffffffu, v, o));
    return v;
}
__device__ __forceinline__ float wsum(float v) {
#pragma unroll
    for (int o = 16; o; o >>= 1) v += __shfl_xor_sync(0xffffffffu, v, o);
    return v;
}
__device__ __forceinline__ float lrelu(float e) { return e > 0.f ? e : 0.2f * e; }

__device__ __forceinline__ int clampN(int v) {
    return v < 0 ? 0 : (v >= NN ? NN - 1 : v);
}

__device__ __forceinline__ int edge_at(const void* ei, int i) {
    if (g_is64) return (int)((const long long*)ei)[i];
    return ((const int*)ei)[i];
}

// ---------------- dtype detect + zero -------------------------------------
__global__ void k_zero() {
    int i = blockIdx.x * blockDim.x + threadIdx.x;
    if (i == 0) g_is64 = 1;
    if (i < NN) { g_cnt[i] = 0; g_cur[i] = 0; }
}

__global__ void k_detect(const long long* __restrict__ ei) {
    int i = blockIdx.x * blockDim.x + threadIdx.x;
    if (i >= EE) return;
    long long v = ei[i];
    if (v < 0 || v >= NN) g_is64 = 0;
}

// ---------------- CSR build -----------------------------------------------
__global__ void k_count(const void* __restrict__ ei) {
    int i = blockIdx.x * blockDim.x + threadIdx.x;
    if (i >= EP) return;
    int d = (i < EE) ? clampN(edge_at(ei, EE + i)) : (i - EE);
    atomicAdd(&g_cnt[d], 1);
}

__global__ void k_scan1() {
    __shared__ int sh[SCAN_B];
    int t = threadIdx.x, b = blockIdx.x;
    int i = b * SCAN_B + t;
    int v = (i < NN) ? g_cnt[i] : 0;
    sh[t] = v; __syncthreads();
#pragma unroll
    for (int off = 1; off < SCAN_B; off <<= 1) {
        int tv = (t >= off) ? sh[t - off] : 0;
        __syncthreads();
        sh[t] += tv;
        __syncthreads();
    }
    if (i < NN) g_rowptr[i + 1] = sh[t];
    if (t == SCAN_B - 1) g_bsum[b] = sh[t];
}

__global__ void k_scan2() {   // 1 block
    __shared__ int sh[SCAN_NB];
    int t = threadIdx.x;
    if (t < SCAN_NB) sh[t] = g_bsum[t];
    __syncthreads();
    if (t == 0) {
        int run = 0;
        for (int j = 0; j < SCAN_NB; j++) { g_boff[j] = run; run += sh[j]; }
    }
}

__global__ void k_scan3() {
    int t = threadIdx.x, b = blockIdx.x;
    int i = b * SCAN_B + t;
    if (i < NN) g_rowptr[i + 1] += g_boff[b];
    if (i == 0) g_rowptr[0] = 0;
}

__global__ void k_fill(const void* __restrict__ ei) {
    int i = blockIdx.x * blockDim.x + threadIdx.x;
    if (i >= EP) return;
    int s, d;
    if (i < EE) { s = clampN(edge_at(ei, i)); d = clampN(edge_at(ei, EE + i)); }
    else        { s = i - EE;                 d = i - EE; }
    int pos = g_rowptr[d] + atomicAdd(&g_cur[d], 1);
    g_col[pos] = s;
}

// ---------------- layer 1 GEMM: xh1 = x @ W1 ------------------------------
__global__ void k_gemm1(const float* __restrict__ x, const float* __restrict__ W1) {
    __shared__ float xs[16][FIN];
    int row0 = blockIdx.x * 16;
    int t = threadIdx.x;                 // 256 threads; thread t owns column t
    for (int i = t; i < 16 * FIN; i += 256) {
        int r = i >> 6, c = i & 63;
        int gr = row0 + r;
        xs[r][c] = (gr < NN) ? x[gr * FIN + c] : 0.f;
    }
    __syncthreads();
    float acc[16];
#pragma unroll
    for (int r = 0; r < 16; r++) acc[r] = 0.f;
    for (int k = 0; k < FIN; k++) {
        float w = W1[k * FOUT + t];
#pragma unroll
        for (int r = 0; r < 16; r++) acc[r] += xs[r][k] * w;
    }
    float* xh = (float*)g_xh1;
#pragma unroll
    for (int r = 0; r < 16; r++) {
        int gr = row0 + r;
        if (gr < NN) xh[gr * FOUT + t] = acc[r];
    }
}

// ---------------- attention scalars layer1 --------------------------------
__global__ void k_att1(const float* __restrict__ as1, const float* __restrict__ ad1) {
    int i = blockIdx.x * blockDim.x + threadIdx.x;
    if (i >= NN * 4) return;
    int n = i >> 2, h = i & 3;
    const float* xp = (const float*)g_xh1 + n * FOUT + h * 64;
    const float* ap = as1 + h * 64;
    const float* dp = ad1 + h * 64;
    float s = 0.f, d = 0.f;
#pragma unroll
    for (int k = 0; k < 64; k++) { float v = xp[k]; s += v * ap[k]; d += v * dp[k]; }
    ((float*)g_a_src1)[i] = s;
    ((float*)g_a_dst1)[i] = d;
}

// ---------------- per-edge softmax weights (warp/node, lane-strided) ------
// Two cheap lane-parallel sweeps over scalar logits; writes unnormalized
// weights p to g_alpha[k] and 1/denominator to g_inv1[d].
__global__ void k_att_alpha() {
    int warp = (blockIdx.x * blockDim.x + threadIdx.x) >> 5;
    int lane = threadIdx.x & 31;
    if (warp >= NN) return;
    int d = warp;
    int beg = g_rowptr[d], end = g_rowptr[d + 1];
    float4 adv = g_a_dst1[d];

    float m0 = -1e30f, m1 = -1e30f, m2 = -1e30f, m3 = -1e30f;
    for (int k = beg + lane; k < end; k += 32) {
        float4 av = g_a_src1[g_col[k]];
        m0 = fmaxf(m0, lrelu(av.x + adv.x));
        m1 = fmaxf(m1, lrelu(av.y + adv.y));
        m2 = fmaxf(m2, lrelu(av.z + adv.z));
        m3 = fmaxf(m3, lrelu(av.w + adv.w));
    }
    m0 = wmax(m0); m1 = wmax(m1); m2 = wmax(m2); m3 = wmax(m3);

    float s0 = 0.f, s1 = 0.f, s2 = 0.f, s3 = 0.f;
    for (int k = beg + lane; k < end; k += 32) {
        float4 av = g_a_src1[g_col[k]];
        float4 p;
        p.x = __expf(lrelu(av.x + adv.x) - m0);
        p.y = __expf(lrelu(av.y + adv.y) - m1);
        p.z = __expf(lrelu(av.z + adv.z) - m2);
        p.w = __expf(lrelu(av.w + adv.w) - m3);
        g_alpha[k] = p;
        s0 += p.x; s1 += p.y; s2 += p.z; s3 += p.w;
    }
    s0 = wsum(s0); s1 = wsum(s1); s2 = wsum(s2); s3 = wsum(s3);
    if (lane == 0) {
        float4 iv;
        iv.x = 1.f / (s0 + 1e-16f);
        iv.y = 1.f / (s1 + 1e-16f);
        iv.z = 1.f / (s2 + 1e-16f);
        iv.w = 1.f / (s3 + 1e-16f);
        g_inv1[d] = iv;
    }
}

// ---------------- layer 1 heavy aggregation: pure weighted sum ------------
// warp per dst node. Lane covers cols [4*lane..] (head h0=lane>>4) and
// [128+4*lane..] (head h0+2). Unroll x2 with independent accumulators.
__global__ void k_agg1() {
    int warp = (blockIdx.x * blockDim.x + threadIdx.x) >> 5;
    int lane = threadIdx.x & 31;
    if (warp >= NN) return;
    int d = warp;
    int beg = g_rowptr[d], end = g_rowptr[d + 1];
    int h0 = lane >> 4;
    float4 iv = g_inv1[d];
    float invA = h0 ? iv.y : iv.x;
    float invB = h0 ? iv.w : iv.z;

    float4 a0 = {0,0,0,0}, a1 = {0,0,0,0};   // partial set 0
    float4 b0 = {0,0,0,0}, b1 = {0,0,0,0};   // partial set 1

    int k = beg;
    for (; k + 2 <= end; k += 2) {
        int s0 = g_col[k], s1 = g_col[k + 1];
        float4 al0 = g_alpha[k], al1 = g_alpha[k + 1];
        const float4* p0 = g_xh1 + s0 * 64;
        const float4* p1 = g_xh1 + s1 * 64;
        float4 xa0 = p0[lane], xb0 = p0[32 + lane];
        float4 xa1 = p1[lane], xb1 = p1[32 + lane];
        float wA0 = h0 ? al0.y : al0.x, wB0 = h0 ? al0.w : al0.z;
        float wA1 = h0 ? al1.y : al1.x, wB1 = h0 ? al1.w : al1.z;
        a0.x += xa0.x * wA0; a0.y += xa0.y * wA0; a0.z += xa0.z * wA0; a0.w += xa0.w * wA0;
        a1.x += xb0.x * wB0; a1.y += xb0.y * wB0; a1.z += xb0.z * wB0; a1.w += xb0.w * wB0;
        b0.x += xa1.x * wA1; b0.y += xa1.y * wA1; b0.z += xa1.z * wA1; b0.w += xa1.w * wA1;
        b1.x += xb1.x * wB1; b1.y += xb1.y * wB1; b1.z += xb1.z * wB1; b1.w += xb1.w * wB1;
    }
    if (k < end) {
        int s0 = g_col[k];
        float4 al0 = g_alpha[k];
        const float4* p0 = g_xh1 + s0 * 64;
        float4 xa0 = p0[lane], xb0 = p0[32 + lane];
        float wA0 = h0 ? al0.y : al0.x, wB0 = h0 ? al0.w : al0.z;
        a0.x += xa0.x * wA0; a0.y += xa0.y * wA0; a0.z += xa0.z * wA0; a0.w += xa0.w * wA0;
        a1.x += xb0.x * wB0; a1.y += xb0.y * wB0; a1.z += xb0.z * wB0; a1.w += xb0.w * wB0;
    }
    float4 r0, r1;
    r0.x = (a0.x + b0.x) * invA; r0.y = (a0.y + b0.y) * invA;
    r0.z = (a0.z + b0.z) * invA; r0.w = (a0.w + b0.w) * invA;
    r1.x = (a1.x + b1.x) * invB; r1.y = (a1.y + b1.y) * invB;
    r1.z = (a1.z + b1.z) * invB; r1.w = (a1.w + b1.w) * invB;
    float4* op = g_out1 + d * 64;
    op[lane] = r0;
    op[32 + lane] = r1;
}

// ---------------- layer 2 GEMM: h=elu(out1+b1); xh2=h@W2; a2 scalars ------
__global__ void k_gemm2(const float* __restrict__ b1, const float* __restrict__ W2,
                        const float* __restrict__ as2, const float* __restrict__ ad2) {
    __shared__ float W2s[FOUT * NC];
    __shared__ float hs[16][FOUT];
    __shared__ float xs2[16][NC + 1];
    __shared__ float a2s[NC], a2d[NC];
    int t = threadIdx.x;
    for (int i = t; i < FOUT * NC; i += 256) W2s[i] = W2[i];
    if (t < NC) { a2s[t] = as2[t]; a2d[t] = ad2[t]; }
    int row0 = blockIdx.x * 16;
    const float* o1 = (const float*)g_out1;
    for (int i = t; i < 16 * FOUT; i += 256) {
        int r = i >> 8, k = i & 255;
        int gr = row0 + r;
        float v = (gr < NN) ? o1[gr * FOUT + k] + b1[k] : 0.f;
        hs[r][k] = v > 0.f ? v : (__expf(v) - 1.f);
    }
    __syncthreads();
    int r = t >> 4, c = t & 15;
    int gr = row0 + r;
    float acc = 0.f;
#pragma unroll 8
    for (int k = 0; k < FOUT; k++) acc += hs[r][k] * W2s[k * NC + c];
    if (gr < NN) ((float*)g_xh2)[gr * NC + c] = acc;
    xs2[r][c] = acc;
    __syncthreads();
    if (c < 2 && gr < NN) {
        float s = 0.f;
#pragma unroll
        for (int j = 0; j < NC; j++) s += xs2[r][j] * (c ? a2d[j] : a2s[j]);
        if (c) g_a_dst2[gr] = s; else g_a_src2[gr] = s;
    }
}

// ---------------- layer 2 aggregation (fused online) + log_softmax --------
__global__ void k_agg2(const float* __restrict__ b2, float* __restrict__ out) {
    int warp = (blockIdx.x * blockDim.x + threadIdx.x) >> 5;
    int lane = threadIdx.x & 31;
    if (warp >= NN) return;
    int d = warp;
    int beg = g_rowptr[d], end = g_rowptr[d + 1];
    float adn = g_a_dst2[d];

    float m = -1e30f, ssum = 0.f;
    float acc[NC];
#pragma unroll
    for (int j = 0; j < NC; j++) acc[j] = 0.f;

    for (int k = beg + lane; k < end; k += 32) {
        int s = g_col[k];
        float e = lrelu(g_a_src2[s] + adn);
        float mn = fmaxf(m, e);
        float c = __expf(m - mn);
        float p = __expf(e - mn);
        ssum = ssum * c + p;
        const float4* xp = g_xh2 + s * 4;
        float4 v0 = xp[0], v1 = xp[1], v2 = xp[2], v3 = xp[3];
        acc[0] = acc[0] * c + v0.x * p;  acc[1] = acc[1] * c + v0.y * p;
        acc[2] = acc[2] * c + v0.z * p;  acc[3] = acc[3] * c + v0.w * p;
        acc[4] = acc[4] * c + v1.x * p;  acc[5] = acc[5] * c + v1.y * p;
        acc[6] = acc[6] * c + v1.z * p;  acc[7] = acc[7] * c + v1.w * p;
        acc[8] = acc[8] * c + v2.x * p;  acc[9] = acc[9] * c + v2.y * p;
        acc[10] = acc[10] * c + v2.z * p; acc[11] = acc[11] * c + v2.w * p;
        acc[12] = acc[12] * c + v3.x * p; acc[13] = acc[13] * c + v3.y * p;
        acc[14] = acc[14] * c + v3.z * p; acc[15] = acc[15] * c + v3.w * p;
        m = mn;
    }
    // merge per-lane partials
    float M = wmax(m);
    float corr = __expf(m - M);
    ssum = wsum(ssum * corr);
#pragma unroll
    for (int j = 0; j < NC; j++) acc[j] = wsum(acc[j] * corr);
    float inv = 1.f / (ssum + 1e-16f);

    float l[NC];
    float mm = -1e30f;
#pragma unroll
    for (int j = 0; j < NC; j++) { l[j] = acc[j] * inv + b2[j]; mm = fmaxf(mm, l[j]); }
    float ls = 0.f;
#pragma unroll
    for (int j = 0; j < NC; j++) ls += __expf(l[j] - mm);
    ls = logf(ls) + mm;
    float v = l[0];
#pragma unroll
    for (int j = 1; j < NC; j++) if (lane == j) v = l[j];
    if (lane < NC) out[d * NC + lane] = v - ls;
}

// ---------------- launch ---------------------------------------------------
extern "C" void kernel_launch(void* const* d_in, const int* in_sizes, int n_in,
                              void* d_out, int out_size) {
    const float* x   = (const float*)d_in[0];
    const void*  ei  = d_in[1];
    const float* W1  = (const float*)d_in[2];
    const float* as1 = (const float*)d_in[3];
    const float* ad1 = (const float*)d_in[4];
    const float* b1  = (const float*)d_in[5];
    const float* W2  = (const float*)d_in[6];
    const float* as2 = (const float*)d_in[7];
    const float* ad2 = (const float*)d_in[8];
    const float* b2  = (const float*)d_in[9];
    float* out = (float*)d_out;

    k_zero     <<<(NN + 255) / 256, 256>>>();
    k_detect   <<<(EE + 255) / 256, 256>>>((const long long*)ei);
    k_count    <<<(EP + 255) / 256, 256>>>(ei);
    k_scan1    <<<SCAN_NB, SCAN_B>>>();
    k_scan2    <<<1, 128>>>();
    k_scan3    <<<SCAN_NB, SCAN_B>>>();
    k_fill     <<<(EP + 255) / 256, 256>>>(ei);
    k_gemm1    <<<(NN + 15) / 16, 256>>>(x, W1);
    k_att1     <<<(NN * 4 + 127) / 128, 128>>>(as1, ad1);
    k_att_alpha<<<(NN + 7) / 8, 256>>>();
    k_agg1     <<<(NN + 7) / 8, 256>>>();
    k_gemm2    <<<(NN + 15) / 16, 256>>>(b1, W2, as2, ad2);
    k_agg2     <<<(NN + 7) / 8, 256>>>(b2, out);
}